// round 1
// baseline (speedup 1.0000x reference)
#include <cuda_runtime.h>

#define NNODE 192

// Scratch buffers (device globals — no allocation allowed).
// Max tile: 32*192*32 = 196608 floats.
__device__ float g_bufA[196608];
__device__ float g_bufB[196608];
__device__ float g_bufC[196608];
__device__ float g_bufD[196608];

// Input accessor:
//  mode 0: materialized buffer, layout [t][n][c]   -> x[(t*192+m)*C + c]
//  mode 1: zero-stuffed upsample by 2 + ReLU from a half-T buffer
//  mode 2: raw input X with layout (N, T)          -> x[m*T + t]  (C==1)
__device__ __forceinline__ float acc_in(const float* __restrict__ x, int mode,
                                        int t, int m, int c, int C, int T) {
    if (mode == 0) return x[(t * NNODE + m) * C + c];
    if (mode == 1) {
        if (t & 1) return 0.0f;
        float v = x[((t >> 1) * NNODE + m) * C + c];
        return v > 0.0f ? v : 0.0f;
    }
    return x[m * T + t];
}

// ---------------------------------------------------------------------------
// kshift: xout = S * xin  (one product-graph shift application)
//   (Sx)[t][n][c] = s00*x[t][n][c] + s01*(Sg@x[t])[n][c]
//                 + s10*x[t-1][n][c] + s11*(Sg@x[t-1])[n][c]     (t cyclic)
// grid = (T, C/G); block = 192 threads (one node each), G channels per block.
// ---------------------------------------------------------------------------
template <int G>
__global__ void __launch_bounds__(NNODE)
kshift(const float* __restrict__ xin, float* __restrict__ xout,
       const float* __restrict__ Sg, const float* __restrict__ s4,
       int T, int C, int mode) {
    const int t   = blockIdx.x;
    const int c0  = blockIdx.y * G;
    const int n   = threadIdx.x;
    const int tm1 = (t + T - 1) % T;

    __shared__ float xt[NNODE * G];
    __shared__ float xm[NNODE * G];

    for (int idx = n; idx < NNODE * G; idx += NNODE) {
        const int m = idx / G;
        const int j = idx - m * G;
        xt[idx] = acc_in(xin, mode, t,   m, c0 + j, C, T);
        xm[idx] = acc_in(xin, mode, tm1, m, c0 + j, C, T);
    }
    __syncthreads();

    float a0[G], a1[G];
#pragma unroll
    for (int j = 0; j < G; j++) { a0[j] = 0.0f; a1[j] = 0.0f; }

    const float* __restrict__ row = Sg + n * NNODE;
#pragma unroll 4
    for (int m = 0; m < NNODE; m++) {
        const float sg = row[m];
#pragma unroll
        for (int j = 0; j < G; j++) {
            a0[j] = fmaf(sg, xt[m * G + j], a0[j]);
            a1[j] = fmaf(sg, xm[m * G + j], a1[j]);
        }
    }

    const float s00 = s4[0], s01 = s4[1], s10 = s4[2], s11 = s4[3];
#pragma unroll
    for (int j = 0; j < G; j++) {
        float v = s00 * xt[n * G + j] + s01 * a0[j]
                + s10 * xm[n * G + j] + s11 * a1[j];
        xout[(t * NNODE + n) * C + c0 + j] = v;
    }
}

// ---------------------------------------------------------------------------
// kproj: Y[t][n][o] = sum_c ( X0*h[o][c][0] + X1*h[o][c][1] + X2*h[o][c][2] )
// Epilogue:
//   emode 0: max-pool over time pairs + ReLU, write [p][n][o]  (grid.x = T/2)
//   emode 1: plain write [t][n][o]                              (grid.x = T)
//   emode 2: COUT==1, transpose write out[n*T + t]              (grid.x = T)
// ---------------------------------------------------------------------------
template <int CIN, int COUT>
__global__ void __launch_bounds__(NNODE)
kproj(const float* __restrict__ x0in, const float* __restrict__ x1,
      const float* __restrict__ x2, const float* __restrict__ h,
      float* __restrict__ out, int T, int mode0, int emode) {
    __shared__ float hs[COUT * CIN * 3];
    const int n = threadIdx.x;
    for (int idx = n; idx < COUT * CIN * 3; idx += NNODE) hs[idx] = h[idx];
    __syncthreads();

    const int nt    = (emode == 0) ? 2 : 1;
    const int tbase = (emode == 0) ? blockIdx.x * 2 : blockIdx.x;

    float best[COUT];
#pragma unroll
    for (int o = 0; o < COUT; o++) best[o] = -3.0e38f;

    for (int it = 0; it < nt; it++) {
        const int t = tbase + it;
        float y[COUT];
#pragma unroll
        for (int o = 0; o < COUT; o++) y[o] = 0.0f;

        for (int c = 0; c < CIN; c++) {
            const float v0 = acc_in(x0in, mode0, t, n, c, CIN, T);
            const float v1 = x1[(t * NNODE + n) * CIN + c];
            const float v2 = x2[(t * NNODE + n) * CIN + c];
#pragma unroll
            for (int o = 0; o < COUT; o++) {
                const float* hp = &hs[(o * CIN + c) * 3];
                y[o] = fmaf(v0, hp[0], y[o]);
                y[o] = fmaf(v1, hp[1], y[o]);
                y[o] = fmaf(v2, hp[2], y[o]);
            }
        }

        if (emode == 0) {
#pragma unroll
            for (int o = 0; o < COUT; o++) best[o] = fmaxf(best[o], y[o]);
        } else if (emode == 1) {
#pragma unroll
            for (int o = 0; o < COUT; o++)
                out[(t * NNODE + n) * COUT + o] = y[o];
        } else {
            out[n * T + t] = y[0];
        }
    }

    if (emode == 0) {
        const int p = blockIdx.x;
#pragma unroll
        for (int o = 0; o < COUT; o++)
            out[(p * NNODE + n) * COUT + o] = fmaxf(best[o], 0.0f);
    }
}

extern "C" void kernel_launch(void* const* d_in, const int* in_sizes, int n_in,
                              void* d_out, int out_size) {
    const float* X   = (const float*)d_in[0];  // (192, 32)
    const float* Sg  = (const float*)d_in[1];  // (192, 192)
    const float* s   = (const float*)d_in[2];  // (2, 2)
    const float* he1 = (const float*)d_in[3];  // (16, 1, 3)
    const float* he2 = (const float*)d_in[4];  // (32, 16, 3)
    const float* hd1 = (const float*)d_in[5];  // (16, 32, 3)
    const float* hd2 = (const float*)d_in[6];  // (1, 16, 3)
    float* out = (float*)d_out;                // (192, 32)

    float *bA, *bB, *bC, *bD;
    cudaGetSymbolAddress((void**)&bA, g_bufA);
    cudaGetSymbolAddress((void**)&bB, g_bufB);
    cudaGetSymbolAddress((void**)&bC, g_bufC);
    cudaGetSymbolAddress((void**)&bD, g_bufD);

    // ---- Encoder layer 1: T=32, Cin=1 -> Cout=16, pool -> (16,192,16) in bC
    kshift<1><<<dim3(32, 1), NNODE>>>(X,  bA, Sg, s, 32, 1, 2);  // X1
    kshift<1><<<dim3(32, 1), NNODE>>>(bA, bB, Sg, s, 32, 1, 0);  // X2
    kproj<1, 16><<<16, NNODE>>>(X, bA, bB, he1, bC, 32, 2, 0);

    // ---- Encoder layer 2: T=16, Cin=16 -> Cout=32, pool -> (8,192,32) in bD
    kshift<8><<<dim3(16, 2), NNODE>>>(bC, bA, Sg, s, 16, 16, 0);
    kshift<8><<<dim3(16, 2), NNODE>>>(bA, bB, Sg, s, 16, 16, 0);
    kproj<16, 32><<<8, NNODE>>>(bC, bA, bB, he2, bD, 16, 0, 0);

    // ---- Decoder layer 1: upsample 8->16 (+ReLU in accessor), Cin=32 -> Cout=16
    //      plain output -> (16,192,16) in bC
    kshift<8><<<dim3(16, 4), NNODE>>>(bD, bA, Sg, s, 16, 32, 1);
    kshift<8><<<dim3(16, 4), NNODE>>>(bA, bB, Sg, s, 16, 32, 0);
    kproj<32, 16><<<16, NNODE>>>(bD, bA, bB, hd1, bC, 16, 1, 1);

    // ---- Decoder layer 2: upsample 16->32 (+ReLU), Cin=16 -> Cout=1
    //      transpose write to d_out (N, T)
    kshift<8><<<dim3(32, 2), NNODE>>>(bC, bA, Sg, s, 32, 16, 1);
    kshift<8><<<dim3(32, 2), NNODE>>>(bA, bB, Sg, s, 32, 16, 0);
    kproj<16, 1><<<32, NNODE>>>(bC, bA, bB, hd2, out, 32, 1, 2);
}

// round 2
// speedup vs baseline: 2.4794x; 2.4794x over previous
#include <cuda_runtime.h>

#define NN 192

// Scratch (device globals — no allocation allowed).
__device__ float g_SgT[NN * NN];   // transposed shift matrix
__device__ float g_A[98304];       // g0 = Sg @ x0
__device__ float g_B[98304];       // x1
__device__ float g_C[98304];       // g1 = Sg @ x1
__device__ float g_P1[49152];      // encoder1 out (pooled, relu)  [t][c][n]
__device__ float g_P2[49152];      // encoder2 out (pooled, relu)
__device__ float g_P3[49152];      // decoder1 out (no relu)

// ---------------------------------------------------------------------------
// One-time transpose: SgT[m][n] = Sg[n][m]  (enables coalesced streaming)
// ---------------------------------------------------------------------------
__global__ void __launch_bounds__(NN) ktrans(const float* __restrict__ Sg,
                                             float* __restrict__ SgT) {
    const int m = blockIdx.x, n = threadIdx.x;
    SgT[m * NN + n] = Sg[n * NN + m];
}

// x0 accessors (element (t, c, m)):
//  X0M 0: raw input X, layout (N=192, T=32):   X[m*32 + t]   (c==0)
//  X0M 1: buffer [t][c][m]
//  X0M 5: decoder upsample+relu: odd t -> 0; even -> relu(P[(t/2)*C+c][m])
template <int X0M>
__device__ __forceinline__ float x0val(const float* __restrict__ P,
                                       int t, int c, int m, int C) {
    if (X0M == 0) return P[m * 32 + t];
    if (X0M == 1) return P[(t * C + c) * NN + m];
    // X0M == 5
    if (t & 1) return 0.0f;
    float v = P[(((t >> 1) * C + c)) * NN + m];
    return v > 0.0f ? v : 0.0f;
}

// ---------------------------------------------------------------------------
// kgemm: Gout[p][n] = sum_m SgT[m][n] * x(p, m)  for TCT pairs p per block.
// Pair p -> (t = p/C, c = p%C).
// XMODE:
//  0: x = raw X            (encoder1 KA)
//  1: x = buffer plain     (encoder2 KA)
//  2: x = relu(buffer)     (decoder KA; t is compact even-time index)
//  3: x = x1 built from x0(X0M in {0,1}) and g0 buffer, cyclic T  (encoder KB)
//  4: x = x1 decoder: x0 = up+relu(P), g0 = compact even-time A   (decoder KB)
// For KB modes, x1 is also persisted to X1out.
// ---------------------------------------------------------------------------
template <int TCT, int XMODE, int X0M>
__global__ void __launch_bounds__(NN)
kgemm(const float* __restrict__ SgT, const float* __restrict__ P,
      const float* __restrict__ G0, const float* __restrict__ s4,
      float* __restrict__ Gout, float* __restrict__ X1out, int C, int T) {
    const int n  = threadIdx.x;
    const int p0 = blockIdx.x * TCT;
    __shared__ float xs[TCT * NN];

    float s00 = 0, s01 = 0, s10 = 0, s11 = 0;
    if (XMODE >= 3) { s00 = s4[0]; s01 = s4[1]; s10 = s4[2]; s11 = s4[3]; }

#pragma unroll
    for (int j = 0; j < TCT; j++) {
        const int pp = p0 + j;
        const int t = pp / C, c = pp % C;
        float v;
        if (XMODE == 0) {
            v = P[n * 32 + t];
        } else if (XMODE == 1) {
            v = P[(t * C + c) * NN + n];
        } else if (XMODE == 2) {
            v = P[(t * C + c) * NN + n];
            v = v > 0.0f ? v : 0.0f;
        } else if (XMODE == 3) {
            const int tm = (t + T - 1) % T;
            const float x0t = x0val<X0M>(P, t,  c, n, C);
            const float x0m = x0val<X0M>(P, tm, c, n, C);
            v = s00 * x0t + s01 * G0[(t * C + c) * NN + n]
              + s10 * x0m + s11 * G0[(tm * C + c) * NN + n];
        } else {  // XMODE == 4 (decoder KB)
            const int tm = (t + T - 1) % T;
            float x0t = 0, g0t = 0, x0m = 0, g0m = 0;
            if (!(t & 1)) {
                float u = P[(((t >> 1) * C + c)) * NN + n];
                x0t = u > 0.0f ? u : 0.0f;
                g0t = G0[(((t >> 1) * C + c)) * NN + n];
            }
            if (!(tm & 1)) {
                float u = P[(((tm >> 1) * C + c)) * NN + n];
                x0m = u > 0.0f ? u : 0.0f;
                g0m = G0[(((tm >> 1) * C + c)) * NN + n];
            }
            v = s00 * x0t + s01 * g0t + s10 * x0m + s11 * g0m;
        }
        xs[j * NN + n] = v;
        if (X1out) X1out[(p0 + j) * NN + n] = v;
    }
    __syncthreads();

    float acc[TCT];
#pragma unroll
    for (int j = 0; j < TCT; j++) acc[j] = 0.0f;

    const float* __restrict__ sr = SgT + n;
#pragma unroll 8
    for (int m = 0; m < NN; m++) {
        const float sg = sr[m * NN];  // coalesced across n
#pragma unroll
        for (int j = 0; j < TCT; j++)
            acc[j] = fmaf(sg, xs[j * NN + m], acc[j]);
    }
#pragma unroll
    for (int j = 0; j < TCT; j++) Gout[(p0 + j) * NN + n] = acc[j];
}

// ---------------------------------------------------------------------------
// kproj: Y[t][n][o] = sum_c x0*h[o][c][0] + x1*h[o][c][1] + x2*h[o][c][2]
//   x2 synthesized: s00*x1[t] + s01*g1[t] + s10*x1[t-1] + s11*g1[t-1]
// EMODE 0: pool pairs + relu -> out[(p*COUT+o)*NN+n]
// EMODE 1: plain            -> out[(t*COUT+o)*NN+n]
// EMODE 2: COUT==1, transpose -> out[n*T + t]
// blockIdx.y covers COUT in groups of OG.
// ---------------------------------------------------------------------------
template <int CIN, int COUT, int OG, int EMODE, int X0M>
__global__ void __launch_bounds__(NN)
kproj(const float* __restrict__ P, const float* __restrict__ X1,
      const float* __restrict__ G1, const float* __restrict__ h,
      const float* __restrict__ s4, float* __restrict__ out, int T) {
    const int n  = threadIdx.x;
    const int o0 = blockIdx.y * OG;
    __shared__ float hs[OG * CIN * 3];
    for (int idx = n; idx < OG * CIN * 3; idx += NN)
        hs[idx] = h[o0 * CIN * 3 + idx];
    __syncthreads();

    const float s00 = s4[0], s01 = s4[1], s10 = s4[2], s11 = s4[3];
    const int nt = (EMODE == 0) ? 2 : 1;
    const int tb = (EMODE == 0) ? blockIdx.x * 2 : blockIdx.x;

    float best[OG];
#pragma unroll
    for (int o = 0; o < OG; o++) best[o] = -3.0e38f;

    for (int it = 0; it < nt; it++) {
        const int t  = tb + it;
        const int tm = (t + T - 1) % T;
        float y[OG];
#pragma unroll
        for (int o = 0; o < OG; o++) y[o] = 0.0f;

        for (int c = 0; c < CIN; c++) {
            const float v0  = x0val<X0M>(P, t, c, n, CIN);
            const float v1  = X1[(t  * CIN + c) * NN + n];
            const float g1t = G1[(t  * CIN + c) * NN + n];
            const float v1m = X1[(tm * CIN + c) * NN + n];
            const float g1m = G1[(tm * CIN + c) * NN + n];
            const float v2  = s00 * v1 + s01 * g1t + s10 * v1m + s11 * g1m;
#pragma unroll
            for (int o = 0; o < OG; o++) {
                const float* hp = &hs[(o * CIN + c) * 3];
                y[o] = fmaf(v0, hp[0], y[o]);
                y[o] = fmaf(v1, hp[1], y[o]);
                y[o] = fmaf(v2, hp[2], y[o]);
            }
        }

        if (EMODE == 0) {
#pragma unroll
            for (int o = 0; o < OG; o++) best[o] = fmaxf(best[o], y[o]);
        } else if (EMODE == 1) {
#pragma unroll
            for (int o = 0; o < OG; o++)
                out[(t * COUT + o0 + o) * NN + n] = y[o];
        } else {
            out[n * T + t] = y[0];
        }
    }

    if (EMODE == 0) {
        const int p = blockIdx.x;
#pragma unroll
        for (int o = 0; o < OG; o++)
            out[(p * COUT + o0 + o) * NN + n] = fmaxf(best[o], 0.0f);
    }
}

extern "C" void kernel_launch(void* const* d_in, const int* in_sizes, int n_in,
                              void* d_out, int out_size) {
    const float* X   = (const float*)d_in[0];  // (192, 32)
    const float* Sg  = (const float*)d_in[1];  // (192, 192)
    const float* s   = (const float*)d_in[2];  // (2, 2)
    const float* he1 = (const float*)d_in[3];  // (16, 1, 3)
    const float* he2 = (const float*)d_in[4];  // (32, 16, 3)
    const float* hd1 = (const float*)d_in[5];  // (16, 32, 3)
    const float* hd2 = (const float*)d_in[6];  // (1, 16, 3)
    float* out = (float*)d_out;                // (192, 32)

    float *SgT, *A, *B, *C, *P1, *P2, *P3;
    cudaGetSymbolAddress((void**)&SgT, g_SgT);
    cudaGetSymbolAddress((void**)&A,   g_A);
    cudaGetSymbolAddress((void**)&B,   g_B);
    cudaGetSymbolAddress((void**)&C,   g_C);
    cudaGetSymbolAddress((void**)&P1,  g_P1);
    cudaGetSymbolAddress((void**)&P2,  g_P2);
    cudaGetSymbolAddress((void**)&P3,  g_P3);

    ktrans<<<NN, NN>>>(Sg, SgT);

    // ---- Encoder layer 1: T=32, C=1 -> 16, pool -> P1 (16,16,192)
    kgemm<1, 0, 0><<<32, NN>>>(SgT, X,  nullptr, s, A, nullptr, 1, 32);
    kgemm<1, 3, 0><<<32, NN>>>(SgT, X,  A,       s, C, B,       1, 32);
    kproj<1, 16, 8, 0, 0><<<dim3(16, 2), NN>>>(X, B, C, he1, s, P1, 32);

    // ---- Encoder layer 2: T=16, C=16 -> 32, pool -> P2 (8,32,192)
    kgemm<2, 1, 0><<<128, NN>>>(SgT, P1, nullptr, s, A, nullptr, 16, 16);
    kgemm<2, 3, 1><<<128, NN>>>(SgT, P1, A,       s, C, B,       16, 16);
    kproj<16, 32, 8, 0, 1><<<dim3(8, 4), NN>>>(P1, B, C, he2, s, P2, 16);

    // ---- Decoder layer 1: up 8->16 (+relu), C=32 -> 16, plain -> P3 (16,16,192)
    //      KA only over even timesteps (compact index 0..7)
    kgemm<2, 2, 0><<<128, NN>>>(SgT, P2, nullptr, s, A, nullptr, 32, 8);
    kgemm<4, 4, 0><<<128, NN>>>(SgT, P2, A,       s, C, B,       32, 16);
    kproj<32, 16, 8, 1, 5><<<dim3(16, 2), NN>>>(P2, B, C, hd1, s, P3, 16);

    // ---- Decoder layer 2: up 16->32 (+relu), C=16 -> 1, transpose -> out (192,32)
    kgemm<2, 2, 0><<<128, NN>>>(SgT, P3, nullptr, s, A, nullptr, 16, 16);
    kgemm<4, 4, 0><<<128, NN>>>(SgT, P3, A,       s, C, B,       16, 32);
    kproj<16, 1, 1, 2, 5><<<dim3(32, 1), NN>>>(P3, B, C, hd2, s, out, 32);
}